// round 1
// baseline (speedup 1.0000x reference)
#include <cuda_runtime.h>
#include <math.h>

#define NN 100000
#define NE 1600000
#define NF 512
#define FD 128
#define NC 10
#define OUTC 12

// ---------------- scratch (device globals; no allocation) ----------------
__device__ float g_H [(size_t)NN*FD];
__device__ float g_E1[(size_t)NN*FD];
__device__ float g_E2[(size_t)NN*FD];
__device__ float g_E3[(size_t)NN*FD];
__device__ float g_T [(size_t)NN*FD];
__device__ float g_C10[(size_t)NN*NC];
__device__ int   g_cnt [2*NN];
__device__ float g_dis [2*NN];
__device__ float g_invd[2*NN];
__device__ int   g_off [2*(NN+1)];
__device__ int   g_cur [2*NN];
__device__ int   g_ssrc[2*NE];
__device__ float g_sw  [2*NE];

// ---------------- degree count ----------------
__global__ void k_count(const int* __restrict__ dst, int* __restrict__ cnt) {
    int i = blockIdx.x * blockDim.x + threadIdx.x;
    if (i < NE) atomicAdd(&cnt[dst[i]], 1);
}

__global__ void k_deg(const int* __restrict__ cnt, float* __restrict__ dis,
                      float* __restrict__ invd) {
    int i = blockIdx.x * blockDim.x + threadIdx.x;
    if (i < NN) {
        float d = (float)(cnt[i] + 1);
        dis[i]  = rsqrtf(d);
        invd[i] = 1.0f / d;
    }
}

// ---------------- single-block exclusive scan (NN=100k, 98 chunks) ----------------
__global__ void k_scan(const int* __restrict__ cnt, int* __restrict__ off,
                       int* __restrict__ cur) {
    __shared__ int sh[1024];
    __shared__ int sbase;
    int t = threadIdx.x;
    if (t == 0) sbase = 0;
    __syncthreads();
    for (int start = 0; start < NN; start += 1024) {
        int i = start + t;
        int v = (i < NN) ? cnt[i] : 0;
        sh[t] = v;
        __syncthreads();
        #pragma unroll
        for (int d = 1; d < 1024; d <<= 1) {
            int tv = (t >= d) ? sh[t - d] : 0;
            __syncthreads();
            sh[t] += tv;
            __syncthreads();
        }
        int incl = sh[t];
        int base = sbase;
        if (i < NN) { off[i] = base + incl - v; cur[i] = base + incl - v; }
        __syncthreads();
        if (t == 1023) sbase = base + sh[1023];
        __syncthreads();
    }
    if (t == 0) off[NN] = sbase;
}

// ---------------- edge placement (counting sort by dst) ----------------
__global__ void k_place(const int* __restrict__ src, const int* __restrict__ dst,
                        const float* __restrict__ dis, int* __restrict__ cur,
                        int* __restrict__ ssrc, float* __restrict__ sw) {
    int e = blockIdx.x * blockDim.x + threadIdx.x;
    if (e < NE) {
        int s = src[e], d = dst[e];
        int p = atomicAdd(&cur[d], 1);
        ssrc[p] = s;
        sw[p]   = dis[s] * dis[d];
    }
}

// ---------------- SGEMM: C[M,128] = A[M,K] @ B[K,128], packed f32x2 FMAs ----
// BM=64, BN=128, BK=32, 128 threads, TM=8, TN=8. Optional row gather (perm),
// optional bias, optional relu.
__global__ __launch_bounds__(128) void k_gemm128(
    const float* __restrict__ A, const int* __restrict__ perm,
    const float* __restrict__ B, const float* __restrict__ bias,
    float* __restrict__ C, int M, int K, int dorelu)
{
    __shared__ float As[32 * 68];    // [k][m], padded
    __shared__ float Bs[32 * 132];   // [k][n], padded

    const int tid = threadIdx.x;
    const int m0  = blockIdx.x * 64;

    // A-load geometry: 8 float4 cols x 16 rows per pass, 4 passes
    const int acol4 = (tid & 7) * 4;
    const int rbase = tid >> 3;
    int arow[4];
    #pragma unroll
    for (int p = 0; p < 4; p++) {
        int gr = m0 + rbase + p * 16;
        if (gr >= M) gr = M - 1;
        arow[p] = perm ? perm[gr] : gr;
    }
    // B-load geometry
    const int bc  = (tid & 31) * 4;
    const int bk0 = tid >> 5;

    const int tm = (tid >> 4) * 8;
    const int tn = (tid & 15) * 8;

    unsigned long long acc[8][4];
    #pragma unroll
    for (int i = 0; i < 8; i++)
        #pragma unroll
        for (int j = 0; j < 4; j++) acc[i][j] = 0ULL;

    for (int k0 = 0; k0 < K; k0 += 32) {
        #pragma unroll
        for (int p = 0; p < 4; p++) {
            int r = rbase + p * 16;
            float4 v = *(const float4*)(A + (size_t)arow[p] * K + k0 + acol4);
            As[(acol4 + 0) * 68 + r] = v.x;
            As[(acol4 + 1) * 68 + r] = v.y;
            As[(acol4 + 2) * 68 + r] = v.z;
            As[(acol4 + 3) * 68 + r] = v.w;
        }
        #pragma unroll
        for (int p = 0; p < 8; p++) {
            int kk = bk0 + p * 4;
            *(float4*)&Bs[kk * 132 + bc] =
                *(const float4*)(B + (size_t)(k0 + kk) * FD + bc);
        }
        __syncthreads();

        #pragma unroll 8
        for (int k = 0; k < 32; k++) {
            float4 a0 = *(const float4*)&As[k * 68 + tm];
            float4 a1 = *(const float4*)&As[k * 68 + tm + 4];
            const unsigned long long* bp =
                (const unsigned long long*)&Bs[k * 132 + tn];
            unsigned long long b0 = bp[0], b1 = bp[1], b2 = bp[2], b3 = bp[3];
            float av[8] = {a0.x, a0.y, a0.z, a0.w, a1.x, a1.y, a1.z, a1.w};
            #pragma unroll
            for (int i = 0; i < 8; i++) {
                unsigned long long a2;
                unsigned int ai = __float_as_uint(av[i]);
                asm("mov.b64 %0, {%1, %1};" : "=l"(a2) : "r"(ai));
                asm("fma.rn.f32x2 %0, %1, %2, %3;"
                    : "=l"(acc[i][0]) : "l"(a2), "l"(b0), "l"(acc[i][0]));
                asm("fma.rn.f32x2 %0, %1, %2, %3;"
                    : "=l"(acc[i][1]) : "l"(a2), "l"(b1), "l"(acc[i][1]));
                asm("fma.rn.f32x2 %0, %1, %2, %3;"
                    : "=l"(acc[i][2]) : "l"(a2), "l"(b2), "l"(acc[i][2]));
                asm("fma.rn.f32x2 %0, %1, %2, %3;"
                    : "=l"(acc[i][3]) : "l"(a2), "l"(b3), "l"(acc[i][3]));
            }
        }
        __syncthreads();
    }

    float bs[8] = {0, 0, 0, 0, 0, 0, 0, 0};
    if (bias) {
        float4 t0 = *(const float4*)(bias + tn);
        float4 t1 = *(const float4*)(bias + tn + 4);
        bs[0] = t0.x; bs[1] = t0.y; bs[2] = t0.z; bs[3] = t0.w;
        bs[4] = t1.x; bs[5] = t1.y; bs[6] = t1.z; bs[7] = t1.w;
    }
    #pragma unroll
    for (int i = 0; i < 8; i++) {
        int gr = m0 + tm + i;
        if (gr < M) {
            float o[8];
            #pragma unroll
            for (int j = 0; j < 4; j++) {
                unsigned long long v = acc[i][j];
                o[2 * j + 0] = __uint_as_float((unsigned int)v) + bs[2 * j + 0];
                o[2 * j + 1] = __uint_as_float((unsigned int)(v >> 32)) + bs[2 * j + 1];
            }
            if (dorelu) {
                #pragma unroll
                for (int j = 0; j < 8; j++) o[j] = fmaxf(o[j], 0.0f);
            }
            float* cp = C + (size_t)gr * FD + tn;
            *(float4*)(cp)     = make_float4(o[0], o[1], o[2], o[3]);
            *(float4*)(cp + 4) = make_float4(o[4], o[5], o[6], o[7]);
        }
    }
}

// ---------------- gather aggregation, 128-dim, warp per node ----------------
__global__ void k_agg(const float* __restrict__ h, const int* __restrict__ off,
                      const int* __restrict__ ssrc, const float* __restrict__ sw,
                      const float* __restrict__ invd, const float* __restrict__ bias,
                      float* __restrict__ outb, int dorelu)
{
    int node = (blockIdx.x * blockDim.x + threadIdx.x) >> 5;
    int lane = threadIdx.x & 31;
    if (node >= NN) return;
    int s = off[node], e = off[node + 1];
    float4 acc = make_float4(0.f, 0.f, 0.f, 0.f);
    for (int i = s; i < e; i++) {
        int   src = ssrc[i];
        float w   = sw[i];
        float4 v  = *(const float4*)(h + (size_t)src * FD + lane * 4);
        acc.x = fmaf(w, v.x, acc.x);
        acc.y = fmaf(w, v.y, acc.y);
        acc.z = fmaf(w, v.z, acc.z);
        acc.w = fmaf(w, v.w, acc.w);
    }
    float  id = invd[node];
    float4 hv = *(const float4*)(h + (size_t)node * FD + lane * 4);
    float4 b  = *(const float4*)(bias + lane * 4);
    acc.x = fmaf(id, hv.x, acc.x) + b.x;
    acc.y = fmaf(id, hv.y, acc.y) + b.y;
    acc.z = fmaf(id, hv.z, acc.z) + b.z;
    acc.w = fmaf(id, hv.w, acc.w) + b.w;
    if (dorelu) {
        acc.x = fmaxf(acc.x, 0.f); acc.y = fmaxf(acc.y, 0.f);
        acc.z = fmaxf(acc.z, 0.f); acc.w = fmaxf(acc.w, 0.f);
    }
    *(float4*)(outb + (size_t)node * FD + lane * 4) = acc;
}

// ---------------- classifier GEMM: C[M,10] = A[M,128] @ W[128,10] ----------
__global__ void k_gemm10(const float* __restrict__ A, const float* __restrict__ W,
                         float* __restrict__ C)
{
    __shared__ float w[FD * NC];
    for (int i = threadIdx.x; i < FD * NC; i += blockDim.x) w[i] = W[i];
    __syncthreads();
    int r = blockIdx.x * blockDim.x + threadIdx.x;
    if (r >= NN) return;
    float acc[NC];
    #pragma unroll
    for (int j = 0; j < NC; j++) acc[j] = 0.f;
    const float4* ap = (const float4*)(A + (size_t)r * FD);
    #pragma unroll 8
    for (int k4 = 0; k4 < 32; k4++) {
        float4 v = ap[k4];
        int k = k4 * 4;
        #pragma unroll
        for (int j = 0; j < NC; j++) {
            acc[j] = fmaf(v.x, w[(k + 0) * NC + j], acc[j]);
            acc[j] = fmaf(v.y, w[(k + 1) * NC + j], acc[j]);
            acc[j] = fmaf(v.z, w[(k + 2) * NC + j], acc[j]);
            acc[j] = fmaf(v.w, w[(k + 3) * NC + j], acc[j]);
        }
    }
    #pragma unroll
    for (int j = 0; j < NC; j++) C[(size_t)r * NC + j] = acc[j];
}

// ---------------- classifier aggregation -> out cols [0..9] ----------------
__global__ void k_agg10(const float* __restrict__ h, const int* __restrict__ off,
                        const int* __restrict__ ssrc, const float* __restrict__ sw,
                        const float* __restrict__ invd, const float* __restrict__ bc,
                        float* __restrict__ out)
{
    int node = (blockIdx.x * blockDim.x + threadIdx.x) >> 5;
    int lane = threadIdx.x & 31;
    if (node >= NN || lane >= NC) return;
    int s = off[node], e = off[node + 1];
    float acc = 0.f;
    for (int i = s; i < e; i++) {
        int src = ssrc[i];
        acc = fmaf(sw[i], h[(size_t)src * NC + lane], acc);
    }
    acc = fmaf(invd[node], h[(size_t)node * NC + lane], acc) + bc[lane];
    out[(size_t)node * OUTC + lane] = acc;
}

// ---------------- score = sigmoid(rowdot(T, E2)) -> out col ----------------
__global__ void k_score(const float* __restrict__ t, const float* __restrict__ e2,
                        float* __restrict__ out, int col)
{
    int row  = (blockIdx.x * blockDim.x + threadIdx.x) >> 5;
    int lane = threadIdx.x & 31;
    if (row >= NN) return;
    float4 a = *(const float4*)(t  + (size_t)row * FD + lane * 4);
    float4 b = *(const float4*)(e2 + (size_t)row * FD + lane * 4);
    float s = a.x * b.x + a.y * b.y + a.z * b.z + a.w * b.w;
    #pragma unroll
    for (int d = 16; d > 0; d >>= 1) s += __shfl_xor_sync(0xffffffffu, s, d);
    if (lane == 0)
        out[(size_t)row * OUTC + col] = 1.0f / (1.0f + expf(-s));
}

// ---------------- host ----------------
extern "C" void kernel_launch(void* const* d_in, const int* in_sizes, int n_in,
                              void* d_out, int out_size)
{
    const float* x    = (const float*)d_in[0];
    const int*   ei   = (const int*)  d_in[1];   // [2, NE]: src, dst
    const int*   eh   = (const int*)  d_in[2];
    const int*   perm = (const int*)  d_in[4];
    const float* W1   = (const float*)d_in[5];
    const float* b1   = (const float*)d_in[6];
    const float* W2   = (const float*)d_in[7];
    const float* b2   = (const float*)d_in[8];
    const float* W3   = (const float*)d_in[9];
    const float* b3   = (const float*)d_in[10];
    const float* M1   = (const float*)d_in[11];
    const float* mb1  = (const float*)d_in[12];
    const float* M2   = (const float*)d_in[13];
    const float* mb2  = (const float*)d_in[14];
    const float* Wc   = (const float*)d_in[15];
    const float* bc   = (const float*)d_in[16];
    const float* Wd   = (const float*)d_in[17];
    float* out = (float*)d_out;

    float *H, *E1, *E2, *E3, *T, *C10, *dis, *invd, *sw;
    int *cnt, *off, *cur, *ssrc;
    cudaGetSymbolAddress((void**)&H,    g_H);
    cudaGetSymbolAddress((void**)&E1,   g_E1);
    cudaGetSymbolAddress((void**)&E2,   g_E2);
    cudaGetSymbolAddress((void**)&E3,   g_E3);
    cudaGetSymbolAddress((void**)&T,    g_T);
    cudaGetSymbolAddress((void**)&C10,  g_C10);
    cudaGetSymbolAddress((void**)&cnt,  g_cnt);
    cudaGetSymbolAddress((void**)&dis,  g_dis);
    cudaGetSymbolAddress((void**)&invd, g_invd);
    cudaGetSymbolAddress((void**)&off,  g_off);
    cudaGetSymbolAddress((void**)&cur,  g_cur);
    cudaGetSymbolAddress((void**)&ssrc, g_ssrc);
    cudaGetSymbolAddress((void**)&sw,   g_sw);

    const int TE = 256;
    const int GE = (NE + TE - 1) / TE;        // edge-parallel grid
    const int GN = (NN + TE - 1) / TE;        // node-parallel grid
    const int GW = (NN * 32 + TE - 1) / TE;   // warp-per-node grid
    const int GB = (NN + 63) / 64;            // GEMM grid

    // ---- CSR build for both edge lists ----
    cudaMemsetAsync(cnt, 0, sizeof(int) * 2 * NN);
    k_count<<<GE, TE>>>(ei + NE, cnt);
    k_count<<<GE, TE>>>(eh + NE, cnt + NN);
    k_deg<<<GN, TE>>>(cnt,      dis,      invd);
    k_deg<<<GN, TE>>>(cnt + NN, dis + NN, invd + NN);
    k_scan<<<1, 1024>>>(cnt,      off,            cur);
    k_scan<<<1, 1024>>>(cnt + NN, off + (NN + 1), cur + NN);
    k_place<<<GE, TE>>>(ei, ei + NE, dis,      cur,      ssrc,      sw);
    k_place<<<GE, TE>>>(eh, eh + NE, dis + NN, cur + NN, ssrc + NE, sw + NE);

    // ---- good path: encoder1 (2-layer GCN, relu) ----
    k_gemm128<<<GB, 128>>>(x, nullptr, W1, nullptr, H, NN, NF, 0);
    k_agg<<<GW, TE>>>(H, off, ssrc, sw, invd, b1, E1, 1);
    k_gemm128<<<GB, 128>>>(E1, nullptr, W2, nullptr, H, NN, FD, 0);
    k_agg<<<GW, TE>>>(H, off, ssrc, sw, invd, b2, E1, 1);
    // encoder2 on hop edges (no relu)
    k_gemm128<<<GB, 128>>>(E1, nullptr, W3, nullptr, H, NN, FD, 0);
    k_agg<<<GW, TE>>>(H, off + (NN + 1), ssrc + NE, sw + NE, invd + NN, b3, E2, 0);
    // encoder3 MLP: E3 = relu(E1@M1+mb1)@M2 + mb2
    k_gemm128<<<GB, 128>>>(E1, nullptr, M1, mb1, H, NN, FD, 1);
    k_gemm128<<<GB, 128>>>(H, nullptr, M2, mb2, E3, NN, FD, 0);
    // T = E3 @ Wd[0];  score -> col 10
    k_gemm128<<<GB, 128>>>(E3, nullptr, Wd, nullptr, T, NN, FD, 0);
    k_score<<<GW, TE>>>(T, E2, out, 10);

    // ---- bad path (x[perm]); reuse E3 as embed1_bad, E2 as embed2_bad ----
    k_gemm128<<<GB, 128>>>(x, perm, W1, nullptr, H, NN, NF, 0);
    k_agg<<<GW, TE>>>(H, off, ssrc, sw, invd, b1, E3, 1);
    k_gemm128<<<GB, 128>>>(E3, nullptr, W2, nullptr, H, NN, FD, 0);
    k_agg<<<GW, TE>>>(H, off, ssrc, sw, invd, b2, E3, 1);
    k_gemm128<<<GB, 128>>>(E3, nullptr, W3, nullptr, H, NN, FD, 0);
    k_agg<<<GW, TE>>>(H, off + (NN + 1), ssrc + NE, sw + NE, invd + NN, b3, E2, 0);
    k_score<<<GW, TE>>>(T, E2, out, 11);

    // ---- classifier GCN (feat->10) -> out cols 0..9 ----
    k_gemm10<<<GN, TE>>>(E1, Wc, C10);
    k_agg10<<<GW, TE>>>(C10, off, ssrc, sw, invd, bc, out);
}

// round 4
// speedup vs baseline: 1.4922x; 1.4922x over previous
#include <cuda_runtime.h>
#include <cuda_bf16.h>
#include <math.h>
#include <stdint.h>

#define NN 100000
#define NE 1600000
#define NF 512
#define FD 128
#define NC 10
#define OUTC 12

// ================= PTX helpers (sm_80-compatible only) =================
__device__ __forceinline__ uint32_t s2u(const void* p) {
    uint32_t a;
    asm("{ .reg .u64 t; cvta.to.shared.u64 t, %1; cvt.u32.u64 %0, t; }"
        : "=r"(a) : "l"(p));
    return a;
}
__device__ __forceinline__ void cpa16(uint32_t dst, const void* src) {
    asm volatile("cp.async.cg.shared.global [%0], [%1], 16;" :: "r"(dst), "l"(src));
}
#define CP_COMMIT() asm volatile("cp.async.commit_group;" ::: "memory")
#define CP_WAIT1()  asm volatile("cp.async.wait_group 1;" ::: "memory")
#define CP_WAIT0()  asm volatile("cp.async.wait_group 0;" ::: "memory")

__device__ __forceinline__ void ldsm4(uint32_t* r, uint32_t addr) {
    asm volatile("ldmatrix.sync.aligned.m8n8.x4.shared.b16 {%0,%1,%2,%3}, [%4];"
                 : "=r"(r[0]), "=r"(r[1]), "=r"(r[2]), "=r"(r[3]) : "r"(addr));
}
__device__ __forceinline__ void mma16816(float* c, const uint32_t* a, const uint32_t* b) {
    asm volatile("mma.sync.aligned.m16n8k16.row.col.f32.bf16.bf16.f32 "
                 "{%0,%1,%2,%3}, {%4,%5,%6,%7}, {%8,%9}, {%0,%1,%2,%3};"
                 : "+f"(c[0]), "+f"(c[1]), "+f"(c[2]), "+f"(c[3])
                 : "r"(a[0]), "r"(a[1]), "r"(a[2]), "r"(a[3]), "r"(b[0]), "r"(b[1]));
}

// ================= scratch (device globals) =================
__device__ float g_Hg [(size_t)NN * FD];
__device__ float g_G  [(size_t)NN * FD];
__device__ float g_EAf[(size_t)NN * FD];
__device__ float g_E2 [(size_t)NN * FD];
__device__ float g_T  [(size_t)NN * FD];
__device__ float g_C10[(size_t)NN * NC];
__device__ __nv_bfloat16 g_P1h[(size_t)NN * FD];
__device__ __nv_bfloat16 g_P1l[(size_t)NN * FD];
__device__ __nv_bfloat16 g_P2h[(size_t)NN * FD];
__device__ __nv_bfloat16 g_P2l[(size_t)NN * FD];
__device__ __nv_bfloat16 g_P3h[(size_t)NN * FD];
__device__ __nv_bfloat16 g_P3l[(size_t)NN * FD];
__device__ __nv_bfloat16 g_P4h[(size_t)NN * FD];
__device__ __nv_bfloat16 g_P4l[(size_t)NN * FD];
__device__ __nv_bfloat16 g_xh [(size_t)NN * NF];
__device__ __nv_bfloat16 g_xl [(size_t)NN * NF];
#define WOFF_W1 0
#define WOFF_W2 (128 * 512)
#define WOFF_W3 (WOFF_W2 + 128 * 128)
#define WOFF_M1 (WOFF_W3 + 128 * 128)
#define WOFF_M2 (WOFF_M1 + 128 * 128)
#define WOFF_WD (WOFF_M2 + 128 * 128)
#define WTOT    (WOFF_WD + 128 * 128)
__device__ __nv_bfloat16 g_Wh[WTOT];
__device__ __nv_bfloat16 g_Wl[WTOT];
__device__ int   g_cnt [2 * NN];
__device__ float g_dis [2 * NN];
__device__ float g_invd[2 * NN];
__device__ int   g_off [2 * (NN + 1)];
__device__ int   g_cur [2 * NN];
__device__ int   g_ssrc[2 * NE];
__device__ int   g_ssrcp[NE];
__device__ float g_sw  [2 * NE];

// ================= CSR build =================
__global__ void k_count(const int* __restrict__ dst, int* __restrict__ cnt) {
    int i = blockIdx.x * blockDim.x + threadIdx.x;
    if (i < NE) atomicAdd(&cnt[dst[i]], 1);
}

__global__ void k_deg(const int* __restrict__ cnt, float* __restrict__ dis,
                      float* __restrict__ invd) {
    int i = blockIdx.x * blockDim.x + threadIdx.x;
    if (i < NN) {
        float d = (float)(cnt[i] + 1);
        dis[i]  = rsqrtf(d);
        invd[i] = 1.0f / d;
    }
}

__global__ void k_scan(const int* __restrict__ cnt, int* __restrict__ off,
                       int* __restrict__ cur) {
    __shared__ int wsum[32];
    __shared__ int sbase;
    int t = threadIdx.x, w = t >> 5, l = t & 31;
    if (t == 0) sbase = 0;
    __syncthreads();
    for (int start = 0; start < NN; start += 1024) {
        int i = start + t;
        int v = (i < NN) ? cnt[i] : 0;
        int s = v;
        #pragma unroll
        for (int d = 1; d < 32; d <<= 1) {
            int o = __shfl_up_sync(0xffffffffu, s, d);
            if (l >= d) s += o;
        }
        if (l == 31) wsum[w] = s;
        __syncthreads();
        if (w == 0) {
            int ws = wsum[l];
            #pragma unroll
            for (int d = 1; d < 32; d <<= 1) {
                int o = __shfl_up_sync(0xffffffffu, ws, d);
                if (l >= d) ws += o;
            }
            wsum[l] = ws;
        }
        __syncthreads();
        int base = sbase + (w > 0 ? wsum[w - 1] : 0);
        int excl = base + s - v;
        if (i < NN) { off[i] = excl; cur[i] = excl; }
        int tot = wsum[31];
        __syncthreads();
        if (t == 0) sbase += tot;
        __syncthreads();
    }
    if (t == 0) off[NN] = sbase;
}

__global__ void k_place(const int* __restrict__ src, const int* __restrict__ dst,
                        const float* __restrict__ dis, int* __restrict__ cur,
                        int* __restrict__ ssrc, float* __restrict__ sw) {
    int e = blockIdx.x * blockDim.x + threadIdx.x;
    if (e < NE) {
        int s = src[e], d = dst[e];
        int p = atomicAdd(&cur[d], 1);
        ssrc[p] = s;
        sw[p]   = dis[s] * dis[d];
    }
}

__global__ void k_permsrc(const int* __restrict__ ssrc, const int* __restrict__ perm,
                          int* __restrict__ ssrcp) {
    int i = blockIdx.x * blockDim.x + threadIdx.x;
    if (i < NE) ssrcp[i] = perm[ssrc[i]];
}

// ================= splits =================
__global__ void k_splitx(const float* __restrict__ x, __nv_bfloat16* __restrict__ xh,
                         __nv_bfloat16* __restrict__ xl, int n) {
    int i = blockIdx.x * blockDim.x + threadIdx.x;
    if (i < n) {
        float v = x[i];
        __nv_bfloat16 h = __float2bfloat16(v);
        xh[i] = h;
        xl[i] = __float2bfloat16(v - __bfloat162float(h));
    }
}

// W[K, 128] row-major -> Bt[128, K] (transposed), split hi/lo
__global__ void k_prepw(const float* __restrict__ W, __nv_bfloat16* __restrict__ Bh,
                        __nv_bfloat16* __restrict__ Bl, int K) {
    int i = blockIdx.x * blockDim.x + threadIdx.x;
    if (i < K * 128) {
        int n = i / K, k = i - n * K;
        float v = W[(size_t)k * 128 + n];
        __nv_bfloat16 h = __float2bfloat16(v);
        Bh[(size_t)n * K + k] = h;
        Bl[(size_t)n * K + k] = __float2bfloat16(v - __bfloat162float(h));
    }
}

// ================= mma.sync split-bf16 GEMM =================
// C[M,128] = A[M,K] @ B[K,128].  A: hi/lo bf16 row-major [M,K].
// B: pre-transposed Bt[128,K] hi/lo (col-major for mma row.col).
// D = Ah*Bh + Ah*Bl + Al*Bh accumulated fp32.
// BM=128 BN=128 BK=32, 256 thr, warps 4x2, warp tile 32x64.
// smem row stride 80B (40 bf16): conflict-free ldmatrix, 16B-aligned cp.async.
#define STRIDE_B 80
#define ARR_SZ   (128 * STRIDE_B)        // 10240 B
#define STAGE_SZ (4 * ARR_SZ)            // 40960 B
#define SMEM_SZ  (2 * STAGE_SZ)          // 81920 B

__device__ __forceinline__ void wmma_prefetch(
    uint32_t sbase, const __nv_bfloat16* Ah, const __nv_bfloat16* Al,
    const __nv_bfloat16* Bh, const __nv_bfloat16* Bl,
    int m0, int M, int K, int k0, int tid)
{
    #pragma unroll
    for (int p = 0; p < 2; p++) {
        int idx = tid + p * 256;
        int row = idx >> 2, cg = idx & 3;
        int gr = m0 + row; if (gr >= M) gr = M - 1;
        size_t aoff = (size_t)gr * K + k0 + cg * 8;
        size_t boff = (size_t)row * K + k0 + cg * 8;
        uint32_t so = row * STRIDE_B + cg * 16;
        cpa16(sbase + 0 * ARR_SZ + so, Ah + aoff);
        cpa16(sbase + 1 * ARR_SZ + so, Al + aoff);
        cpa16(sbase + 2 * ARR_SZ + so, Bh + boff);
        cpa16(sbase + 3 * ARR_SZ + so, Bl + boff);
    }
}

__global__ void __launch_bounds__(256, 1) k_wmma(
    const __nv_bfloat16* __restrict__ Ahi, const __nv_bfloat16* __restrict__ Alo,
    const __nv_bfloat16* __restrict__ Bhi, const __nv_bfloat16* __restrict__ Blo,
    const float* __restrict__ bias, int dorelu,
    float* __restrict__ Cf, __nv_bfloat16* __restrict__ Chi,
    __nv_bfloat16* __restrict__ Clo, int M, int K)
{
    extern __shared__ char smem[];
    const uint32_t sb = s2u(smem);
    const int tid  = threadIdx.x;
    const int lane = tid & 31, w = tid >> 5;
    const int wm0 = (w >> 1) * 32, wn0 = (w & 1) * 64;
    const int m0  = blockIdx.x * 128;

    float c[2][8][4];
    #pragma unroll
    for (int i = 0; i < 2; i++)
        #pragma unroll
        for (int j = 0; j < 8; j++)
            #pragma unroll
            for (int q = 0; q < 4; q++) c[i][j][q] = 0.f;

    // ldmatrix per-lane base offsets
    const uint32_t aoffs = (uint32_t)((wm0 + (lane & 15)) * STRIDE_B + (lane >> 4) * 16);
    const uint32_t boffs = (uint32_t)((wn0 + ((lane >> 4) & 1) * 8 + (lane & 7)) * STRIDE_B
                                      + ((lane >> 3) & 1) * 16);

    const int nch = K >> 5;
    wmma_prefetch(sb, Ahi, Alo, Bhi, Blo, m0, M, K, 0, tid);
    CP_COMMIT();

    for (int ch = 0; ch < nch; ch++) {
        if (ch + 1 < nch) {
            wmma_prefetch(sb + ((ch + 1) & 1) * STAGE_SZ, Ahi, Alo, Bhi, Blo,
                          m0, M, K, (ch + 1) << 5, tid);
            CP_COMMIT();
            CP_WAIT1();
        } else {
            CP_WAIT0();
        }
        __syncthreads();

        const uint32_t st = sb + (ch & 1) * STAGE_SZ;
        #pragma unroll
        for (int kk = 0; kk < 2; kk++) {
            const uint32_t kb = kk * 32;
            uint32_t ah[2][4], al[2][4], bh[4][4], bl[4][4];
            #pragma unroll
            for (int mt = 0; mt < 2; mt++) {
                uint32_t ao = st + aoffs + mt * (16 * STRIDE_B) + kb;
                ldsm4(ah[mt], ao + 0 * ARR_SZ);
                ldsm4(al[mt], ao + 1 * ARR_SZ);
            }
            #pragma unroll
            for (int np = 0; np < 4; np++) {
                uint32_t bo = st + boffs + np * (16 * STRIDE_B) + kb;
                ldsm4(bh[np], bo + 2 * ARR_SZ);
                ldsm4(bl[np], bo + 3 * ARR_SZ);
            }
            #pragma unroll
            for (int mt = 0; mt < 2; mt++)
                #pragma unroll
                for (int nt = 0; nt < 8; nt++) {
                    float* cc = c[mt][nt];
                    const uint32_t* ph = &bh[nt >> 1][(nt & 1) * 2];
                    const uint32_t* pl = &bl[nt >> 1][(nt & 1) * 2];
                    mma16816(cc, ah[mt], ph);
                    mma16816(cc, ah[mt], pl);
                    mma16816(cc, al[mt], ph);
                }
        }
        __syncthreads();
    }

    // epilogue
    #pragma unroll
    for (int mt = 0; mt < 2; mt++) {
        #pragma unroll
        for (int part = 0; part < 2; part++) {
            int gr = m0 + wm0 + mt * 16 + (lane >> 2) + part * 8;
            if (gr >= M) continue;
            #pragma unroll
            for (int nt = 0; nt < 8; nt++) {
                int gcol = wn0 + nt * 8 + (lane & 3) * 2;
                float v0 = c[mt][nt][part * 2 + 0];
                float v1 = c[mt][nt][part * 2 + 1];
                if (bias) { v0 += bias[gcol]; v1 += bias[gcol + 1]; }
                if (dorelu) { v0 = fmaxf(v0, 0.f); v1 = fmaxf(v1, 0.f); }
                if (Cf)
                    *(float2*)(Cf + (size_t)gr * FD + gcol) = make_float2(v0, v1);
                if (Chi) {
                    __nv_bfloat16 h0 = __float2bfloat16(v0);
                    __nv_bfloat16 h1 = __float2bfloat16(v1);
                    __nv_bfloat162 hp = __halves2bfloat162(h0, h1);
                    __nv_bfloat162 lp = __halves2bfloat162(
                        __float2bfloat16(v0 - __bfloat162float(h0)),
                        __float2bfloat16(v1 - __bfloat162float(h1)));
                    *(uint32_t*)(Chi + (size_t)gr * FD + gcol) = *(uint32_t*)&hp;
                    *(uint32_t*)(Clo + (size_t)gr * FD + gcol) = *(uint32_t*)&lp;
                }
            }
        }
    }
}

// ================= gather aggregation (128-dim, warp/node) =================
__global__ void k_agg(const float* __restrict__ h, const int* __restrict__ off,
                      const int* __restrict__ ssrc, const float* __restrict__ sw,
                      const float* __restrict__ invd, const float* __restrict__ bias,
                      const int* __restrict__ selfmap,
                      float* __restrict__ outf, __nv_bfloat16* __restrict__ outhi,
                      __nv_bfloat16* __restrict__ outlo, int dorelu)
{
    int node = (blockIdx.x * blockDim.x + threadIdx.x) >> 5;
    int lane = threadIdx.x & 31;
    if (node >= NN) return;
    int s = off[node], e = off[node + 1];
    float4 acc = make_float4(0.f, 0.f, 0.f, 0.f);
    for (int i = s; i < e; i++) {
        int   src = ssrc[i];
        float w   = sw[i];
        float4 v  = *(const float4*)(h + (size_t)src * FD + lane * 4);
        acc.x = fmaf(w, v.x, acc.x);
        acc.y = fmaf(w, v.y, acc.y);
        acc.z = fmaf(w, v.z, acc.z);
        acc.w = fmaf(w, v.w, acc.w);
    }
    int self = selfmap ? selfmap[node] : node;
    float  id = invd[node];
    float4 hv = *(const float4*)(h + (size_t)self * FD + lane * 4);
    float4 b  = *(const float4*)(bias + lane * 4);
    acc.x = fmaf(id, hv.x, acc.x) + b.x;
    acc.y = fmaf(id, hv.y, acc.y) + b.y;
    acc.z = fmaf(id, hv.z, acc.z) + b.z;
    acc.w = fmaf(id, hv.w, acc.w) + b.w;
    if (dorelu) {
        acc.x = fmaxf(acc.x, 0.f); acc.y = fmaxf(acc.y, 0.f);
        acc.z = fmaxf(acc.z, 0.f); acc.w = fmaxf(acc.w, 0.f);
    }
    if (outf)
        *(float4*)(outf + (size_t)node * FD + lane * 4) = acc;
    if (outhi) {
        float vv[4] = {acc.x, acc.y, acc.z, acc.w};
        uint32_t hw[2], lw[2];
        #pragma unroll
        for (int q = 0; q < 2; q++) {
            __nv_bfloat16 ha = __float2bfloat16(vv[2 * q]);
            __nv_bfloat16 hb = __float2bfloat16(vv[2 * q + 1]);
            __nv_bfloat162 hp = __halves2bfloat162(ha, hb);
            __nv_bfloat162 lp = __halves2bfloat162(
                __float2bfloat16(vv[2 * q] - __bfloat162float(ha)),
                __float2bfloat16(vv[2 * q + 1] - __bfloat162float(hb)));
            hw[q] = *(uint32_t*)&hp;
            lw[q] = *(uint32_t*)&lp;
        }
        *(uint2*)(outhi + (size_t)node * FD + lane * 4) = make_uint2(hw[0], hw[1]);
        *(uint2*)(outlo + (size_t)node * FD + lane * 4) = make_uint2(lw[0], lw[1]);
    }
}

// ================= classifier GEMM (128 -> 10) =================
__global__ void k_gemm10(const float* __restrict__ A, const float* __restrict__ W,
                         float* __restrict__ C)
{
    __shared__ float w[FD * NC];
    for (int i = threadIdx.x; i < FD * NC; i += blockDim.x) w[i] = W[i];
    __syncthreads();
    int r = blockIdx.x * blockDim.x + threadIdx.x;
    if (r >= NN) return;
    float acc[NC];
    #pragma unroll
    for (int j = 0; j < NC; j++) acc[j] = 0.f;
    const float4* ap = (const float4*)(A + (size_t)r * FD);
    #pragma unroll 8
    for (int k4 = 0; k4 < 32; k4++) {
        float4 v = ap[k4];
        int k = k4 * 4;
        #pragma unroll
        for (int j = 0; j < NC; j++) {
            acc[j] = fmaf(v.x, w[(k + 0) * NC + j], acc[j]);
            acc[j] = fmaf(v.y, w[(k + 1) * NC + j], acc[j]);
            acc[j] = fmaf(v.z, w[(k + 2) * NC + j], acc[j]);
            acc[j] = fmaf(v.w, w[(k + 3) * NC + j], acc[j]);
        }
    }
    #pragma unroll
    for (int j = 0; j < NC; j++) C[(size_t)r * NC + j] = acc[j];
}

__global__ void k_agg10(const float* __restrict__ h, const int* __restrict__ off,
                        const int* __restrict__ ssrc, const float* __restrict__ sw,
                        const float* __restrict__ invd, const float* __restrict__ bc,
                        float* __restrict__ out)
{
    int node = (blockIdx.x * blockDim.x + threadIdx.x) >> 5;
    int lane = threadIdx.x & 31;
    if (node >= NN || lane >= NC) return;
    int s = off[node], e = off[node + 1];
    float acc = 0.f;
    for (int i = s; i < e; i++) {
        int src = ssrc[i];
        acc = fmaf(sw[i], h[(size_t)src * NC + lane], acc);
    }
    acc = fmaf(invd[node], h[(size_t)node * NC + lane], acc) + bc[lane];
    out[(size_t)node * OUTC + lane] = acc;
}

// ================= score = sigmoid(rowdot(T, E2)) =================
__global__ void k_score(const float* __restrict__ t, const float* __restrict__ e2,
                        float* __restrict__ out, int col)
{
    int row  = (blockIdx.x * blockDim.x + threadIdx.x) >> 5;
    int lane = threadIdx.x & 31;
    if (row >= NN) return;
    float4 a = *(const float4*)(t  + (size_t)row * FD + lane * 4);
    float4 b = *(const float4*)(e2 + (size_t)row * FD + lane * 4);
    float s = a.x * b.x + a.y * b.y + a.z * b.z + a.w * b.w;
    #pragma unroll
    for (int d = 16; d > 0; d >>= 1) s += __shfl_xor_sync(0xffffffffu, s, d);
    if (lane == 0)
        out[(size_t)row * OUTC + col] = 1.0f / (1.0f + expf(-s));
}

// ================= host =================
extern "C" void kernel_launch(void* const* d_in, const int* in_sizes, int n_in,
                              void* d_out, int out_size)
{
    const float* x    = (const float*)d_in[0];
    const int*   ei   = (const int*)  d_in[1];
    const int*   eh   = (const int*)  d_in[2];
    const int*   perm = (const int*)  d_in[4];
    const float* W1   = (const float*)d_in[5];
    const float* b1   = (const float*)d_in[6];
    const float* W2   = (const float*)d_in[7];
    const float* b2   = (const float*)d_in[8];
    const float* W3   = (const float*)d_in[9];
    const float* b3   = (const float*)d_in[10];
    const float* M1   = (const float*)d_in[11];
    const float* mb1  = (const float*)d_in[12];
    const float* M2   = (const float*)d_in[13];
    const float* mb2  = (const float*)d_in[14];
    const float* Wc   = (const float*)d_in[15];
    const float* bc   = (const float*)d_in[16];
    const float* Wd   = (const float*)d_in[17];
    float* out = (float*)d_out;

    float *Hg, *G, *EAf, *E2, *T, *C10, *dis, *invd, *sw;
    __nv_bfloat16 *P1h, *P1l, *P2h, *P2l, *P3h, *P3l, *P4h, *P4l, *xh, *xl, *Wh, *Wl;
    int *cnt, *off, *cur, *ssrc, *ssrcp;
    cudaGetSymbolAddress((void**)&Hg,   g_Hg);
    cudaGetSymbolAddress((void**)&G,    g_G);
    cudaGetSymbolAddress((void**)&EAf,  g_EAf);
    cudaGetSymbolAddress((void**)&E2,   g_E2);
    cudaGetSymbolAddress((void**)&T,    g_T);
    cudaGetSymbolAddress((void**)&C10,  g_C10);
    cudaGetSymbolAddress((void**)&P1h,  g_P1h);
    cudaGetSymbolAddress((void**)&P1l,  g_P1l);
    cudaGetSymbolAddress((void**)&P2h,  g_P2h);
    cudaGetSymbolAddress((void**)&P2l,  g_P2l);
    cudaGetSymbolAddress((void**)&P3h,  g_P3h);
    cudaGetSymbolAddress((void**)&P3l,  g_P3l);
    cudaGetSymbolAddress((void**)&P4h,  g_P4h);
    cudaGetSymbolAddress((void**)&P4l,  g_P4l);
    cudaGetSymbolAddress((void**)&xh,   g_xh);
    cudaGetSymbolAddress((void**)&xl,   g_xl);
    cudaGetSymbolAddress((void**)&Wh,   g_Wh);
    cudaGetSymbolAddress((void**)&Wl,   g_Wl);
    cudaGetSymbolAddress((void**)&cnt,  g_cnt);
    cudaGetSymbolAddress((void**)&dis,  g_dis);
    cudaGetSymbolAddress((void**)&invd, g_invd);
    cudaGetSymbolAddress((void**)&off,  g_off);
    cudaGetSymbolAddress((void**)&cur,  g_cur);
    cudaGetSymbolAddress((void**)&ssrc, g_ssrc);
    cudaGetSymbolAddress((void**)&ssrcp,g_ssrcp);
    cudaGetSymbolAddress((void**)&sw,   g_sw);

    cudaFuncSetAttribute(k_wmma, cudaFuncAttributeMaxDynamicSharedMemorySize, SMEM_SZ);

    const int TE = 256;
    const int GE = (NE + TE - 1) / TE;
    const int GN = (NN + TE - 1) / TE;
    const int GW = (NN * 32 + TE - 1) / TE;
    const int GM = (NN + 127) / 128;

    // ---- CSR build ----
    cudaMemsetAsync(cnt, 0, sizeof(int) * 2 * NN);
    k_count<<<GE, TE>>>(ei + NE, cnt);
    k_count<<<GE, TE>>>(eh + NE, cnt + NN);
    k_deg<<<GN, TE>>>(cnt,      dis,      invd);
    k_deg<<<GN, TE>>>(cnt + NN, dis + NN, invd + NN);
    k_scan<<<1, 1024>>>(cnt,      off,            cur);
    k_scan<<<1, 1024>>>(cnt + NN, off + (NN + 1), cur + NN);
    k_place<<<GE, TE>>>(ei, ei + NE, dis,      cur,      ssrc,      sw);
    k_place<<<GE, TE>>>(eh, eh + NE, dis + NN, cur + NN, ssrc + NE, sw + NE);
    k_permsrc<<<GE, TE>>>(ssrc, perm, ssrcp);

    // ---- splits / weight prep ----
    k_splitx<<<(NN * NF + 255) / 256, 256>>>(x, xh, xl, NN * NF);
    k_prepw<<<(512 * 128 + 255) / 256, 256>>>(W1, Wh + WOFF_W1, Wl + WOFF_W1, 512);
    k_prepw<<<(128 * 128 + 255) / 256, 256>>>(W2, Wh + WOFF_W2, Wl + WOFF_W2, 128);
    k_prepw<<<(128 * 128 + 255) / 256, 256>>>(W3, Wh + WOFF_W3, Wl + WOFF_W3, 128);
    k_prepw<<<(128 * 128 + 255) / 256, 256>>>(M1, Wh + WOFF_M1, Wl + WOFF_M1, 128);
    k_prepw<<<(128 * 128 + 255) / 256, 256>>>(M2, Wh + WOFF_M2, Wl + WOFF_M2, 128);
    k_prepw<<<(128 * 128 + 255) / 256, 256>>>(Wd, Wh + WOFF_WD, Wl + WOFF_WD, 128);

    // ---- good path ----
    k_wmma<<<GM, 256, SMEM_SZ>>>(xh, xl, Wh + WOFF_W1, Wl + WOFF_W1,
                                 nullptr, 0, Hg, nullptr, nullptr, NN, 512);
    k_agg<<<GW, TE>>>(Hg, off, ssrc, sw, invd, b1, nullptr,
                      nullptr, P1h, P1l, 1);
    k_wmma<<<GM, 256, SMEM_SZ>>>(P1h, P1l, Wh + WOFF_W2, Wl + WOFF_W2,
                                 nullptr, 0, G, nullptr, nullptr, NN, 128);
    k_agg<<<GW, TE>>>(G, off, ssrc, sw, invd, b2, nullptr,
                      EAf, P2h, P2l, 1);
    k_wmma<<<GM, 256, SMEM_SZ>>>(P2h, P2l, Wh + WOFF_W3, Wl + WOFF_W3,
                                 nullptr, 0, G, nullptr, nullptr, NN, 128);
    k_agg<<<GW, TE>>>(G, off + (NN + 1), ssrc + NE, sw + NE, invd + NN, b3, nullptr,
                      E2, nullptr, nullptr, 0);
    k_wmma<<<GM, 256, SMEM_SZ>>>(P2h, P2l, Wh + WOFF_M1, Wl + WOFF_M1,
                                 mb1, 1, nullptr, P3h, P3l, NN, 128);
    k_wmma<<<GM, 256, SMEM_SZ>>>(P3h, P3l, Wh + WOFF_M2, Wl + WOFF_M2,
                                 mb2, 0, nullptr, P4h, P4l, NN, 128);
    k_wmma<<<GM, 256, SMEM_SZ>>>(P4h, P4l, Wh + WOFF_WD, Wl + WOFF_WD,
                                 nullptr, 0, T, nullptr, nullptr, NN, 128);
    k_score<<<GW, TE>>>(T, E2, out, 10);

    // ---- bad path: x[perm]@W1 == Hg[perm] (no GEMM) ----
    k_agg<<<GW, TE>>>(Hg, off, ssrcp, sw, invd, b1, perm,
                      nullptr, P1h, P1l, 1);
    k_wmma<<<GM, 256, SMEM_SZ>>>(P1h, P1l, Wh + WOFF_W2, Wl + WOFF_W2,
                                 nullptr, 0, G, nullptr, nullptr, NN, 128);
    k_agg<<<GW, TE>>>(G, off, ssrc, sw, invd, b2, nullptr,
                      nullptr, P2h, P2l, 1);
    k_wmma<<<GM, 256, SMEM_SZ>>>(P2h, P2l, Wh + WOFF_W3, Wl + WOFF_W3,
                                 nullptr, 0, G, nullptr, nullptr, NN, 128);
    k_agg<<<GW, TE>>>(G, off + (NN + 1), ssrc + NE, sw + NE, invd + NN, b3, nullptr,
                      E2, nullptr, nullptr, 0);
    k_score<<<GW, TE>>>(T, E2, out, 11);

    // ---- classifier GCN -> out cols 0..9 ----
    k_gemm10<<<GN, TE>>>(EAf, Wc, C10);
    k_agg10<<<GW, TE>>>(C10, off, ssrc, sw, invd, bc, out);
}